// round 14
// baseline (speedup 1.0000x reference)
#include <cuda_runtime.h>
#include <cuda_fp16.h>
#include <cstdint>
#include <math.h>

#define BATCH   4
#define NSEQ    4096
#define DIM     512
#define MTOT    (BATCH*NSEQ)   // 16384
#define NBT     32             // N column tiles per batch in scores GEMM

// ---------------- scratch (allocation-free rule: device globals) ----------------
__device__ __align__(256) __half g_x16[(size_t)MTOT*DIM];
__device__ __align__(256) __half g_w16[3*DIM*DIM];   // [wq;wk;wv] = [1536,512]
__device__ __align__(256) __half g_Q [(size_t)MTOT*DIM];
__device__ __align__(256) __half g_K [(size_t)MTOT*DIM];
__device__ __align__(256) __half g_Vt[(size_t)BATCH*DIM*NSEQ];
__device__ __align__(256) __half g_P [(size_t)BATCH*NSEQ*NSEQ];   // unnormalized exp(S)
__device__ __align__(256) float  g_ps[(size_t)BATCH*NBT*NSEQ];    // per-CTA row partial sums
__device__ __align__(256) float  g_ri[(size_t)MTOT];              // 1 / row sum

// ---------------- helpers (plain sm_80-level PTX: valid on sm_103 target) -------
__device__ __forceinline__ uint32_t smem_to_u32(const void* p) {
    uint32_t a;
    asm("{ .reg .u64 t; cvta.to.shared.u64 t, %1; cvt.u32.u64 %0, t; }" : "=r"(a) : "l"(p));
    return a;
}
__device__ __forceinline__ void cp16(uint32_t dst, const void* src) {
    asm volatile("cp.async.cg.shared.global [%0], [%1], 16;" :: "r"(dst), "l"(src));
}
#define CP_COMMIT() asm volatile("cp.async.commit_group;")
#define CP_WAIT1()  asm volatile("cp.async.wait_group 1;")

#define LDSM_X4(r0,r1,r2,r3, addr) \
    asm volatile("ldmatrix.sync.aligned.m8n8.x4.shared.b16 {%0,%1,%2,%3}, [%4];" \
        : "=r"(r0), "=r"(r1), "=r"(r2), "=r"(r3) : "r"(addr))

#define MMA16816(d, a, b0, b1) \
    asm volatile("mma.sync.aligned.m16n8k16.row.col.f32.f16.f16.f32 " \
        "{%0,%1,%2,%3}, {%4,%5,%6,%7}, {%8,%9}, {%0,%1,%2,%3};" \
        : "+f"((d)[0]), "+f"((d)[1]), "+f"((d)[2]), "+f"((d)[3]) \
        : "r"((a)[0]), "r"((a)[1]), "r"((a)[2]), "r"((a)[3]), "r"(b0), "r"(b1))

// 16B-chunk XOR swizzle for [rows][64 half] tiles (128B rows, 8 chunks/row)
__device__ __forceinline__ uint32_t swz(int r, int c) {
    return (uint32_t)(r * 128 + ((c ^ (r & 7)) << 4));
}

// FMA-pipe 2^t for t in ~[-4, 4]: round-to-int + deg-5 Taylor on f in [-0.5, 0.5]
// + exponent-bits add. Rel err ~2.4e-6 (<< fp16 store rounding of P).
// Keeps the saturated-MUFU __expf off the scores epilogue critical path.
__device__ __forceinline__ float exp2f_fast(float t) {
    int   ni = __float2int_rn(t);
    float f  = t - (float)ni;
    float p  = 1.3333558146e-3f;            // ln2^5/120
    p = fmaf(p, f, 9.6181291076e-3f);       // ln2^4/24
    p = fmaf(p, f, 5.5504108664e-2f);       // ln2^3/6
    p = fmaf(p, f, 2.4022650696e-1f);       // ln2^2/2
    p = fmaf(p, f, 6.9314718056e-1f);       // ln2
    p = fmaf(p, f, 1.0f);
    return __int_as_float(__float_as_int(p) + (ni << 23));
}

// ---------------------------------------------------------------------------
// fp16 GEMM on mma.sync m16n8k16:  C[M,N] = scale * (A @ B^T)
// A: row-major M x K (fp16), B: row-major N x K (fp16).
// 128x128 CTA tile, BK=64, 3-stage cp.async pipeline in DYNAMIC smem (96KB),
// 4 warps (2m x 2n), 64x64 warp tile, fp32 accumulators, 2-deep register
// fragment pipeline across the 4 k16-steps of each chunk.
// EPI: 3 = exp2(acc*scale) -> fp16 P~ + per-CTA row partial sums
//          (scale carries 1/sqrt(d) * log2(e); exp on the FMA pipe)
//      4 = fp32 out * aux[row]  (row-wise normalization)
//      5 = fused QKV routing: col section 0 -> g_Q (*scale), 1 -> g_K,
//          2 -> g_Vt transposed.
// ---------------------------------------------------------------------------
#define STAGES      3
#define STAGE_BYTES 32768   // A 16KB + B 16KB
#define SMEM_DYN    (STAGES * STAGE_BYTES)

template<int EPI>
__global__ __launch_bounds__(128, 2)
void mma_gemm(const __half* __restrict__ A, const __half* __restrict__ B,
              int K, size_t sA, size_t sB, float scale,
              float* __restrict__ Cf, __half* __restrict__ Ch,
              size_t sC, int ldC, float* __restrict__ aux)
{
    extern __shared__ __align__(1024) char smem[];
    const uint32_t sm0 = smem_to_u32(smem);
    const int tid  = threadIdx.x;
    const int wid  = tid >> 5;
    const int lane = tid & 31;
    const int wm   = wid & 1;        // 0..1  (64-row half)
    const int wn   = wid >> 1;       // 0..1  (64-col half)
    const int bm   = blockIdx.y * 128;
    const int bn   = blockIdx.x * 128;
    const int z    = blockIdx.z;

    const __half* Ap0 = A + (size_t)z * sA + (size_t)bm * K;
    const __half* Bp0 = B + (size_t)z * sB + (size_t)bn * K;

    const int NCH = K >> 6;     // 64-wide k chunks

    float acc[4][8][4];
    #pragma unroll
    for (int i = 0; i < 4; i++)
        #pragma unroll
        for (int j = 0; j < 8; j++)
            #pragma unroll
            for (int e = 0; e < 4; e++) acc[i][j][e] = 0.f;

    // stage load: A 128x64 + B 128x64; 16 cp.async per thread
    auto issue = [&](int i, int s) {
        const __half* Ap = Ap0 + (i << 6);
        const __half* Bp = Bp0 + (i << 6);
        uint32_t sa = sm0 + (uint32_t)s * STAGE_BYTES;
        #pragma unroll
        for (int u = 0; u < 8; u++) {
            int id = tid + u * 128;
            int r  = id >> 3;
            int c  = id & 7;
            uint32_t sw = swz(r, c);
            cp16(sa + sw,         Ap + (size_t)r * K + c * 8);
            cp16(sa + 16384 + sw, Bp + (size_t)r * K + c * 8);
        }
        CP_COMMIT();
    };

    auto ldfrag = [&](uint32_t (*fa)[4], uint32_t (*fb)[4], uint32_t sa, int ks) {
        #pragma unroll
        for (int mi = 0; mi < 4; mi++) {
            int r = wm * 64 + mi * 16 + (lane & 15);
            int c = 2 * ks + (lane >> 4);
            LDSM_X4(fa[mi][0], fa[mi][1], fa[mi][2], fa[mi][3], sa + swz(r, c));
        }
        #pragma unroll
        for (int g = 0; g < 4; g++) {
            int n = wn * 64 + g * 16 + (lane & 7) + ((lane >> 4) & 1) * 8;
            int c = 2 * ks + ((lane >> 3) & 1);
            LDSM_X4(fb[g][0], fb[g][1], fb[g][2], fb[g][3], sa + 16384 + swz(n, c));
        }
    };

    auto mma_all = [&](uint32_t (*fa)[4], uint32_t (*fb)[4]) {
        #pragma unroll
        for (int mi = 0; mi < 4; mi++)
            #pragma unroll
            for (int ni = 0; ni < 8; ni++)
                MMA16816(acc[mi][ni], fa[mi],
                         fb[ni >> 1][(ni & 1) * 2], fb[ni >> 1][(ni & 1) * 2 + 1]);
    };

    uint32_t fa[2][4][4], fb[2][4][4];

    issue(0, 0);
    issue(1, 1);
    CP_WAIT1();
    __syncthreads();
    ldfrag(fa[0], fb[0], sm0, 0);

    for (int i = 0; i < NCH; i++) {
        uint32_t sa = sm0 + (uint32_t)(i % STAGES) * STAGE_BYTES;
        ldfrag(fa[1], fb[1], sa, 1);
        if (i + 2 < NCH) issue(i + 2, (i + 2) % STAGES); else CP_COMMIT();
        mma_all(fa[0], fb[0]);          // ks 0
        ldfrag(fa[0], fb[0], sa, 2);
        mma_all(fa[1], fb[1]);          // ks 1
        ldfrag(fa[1], fb[1], sa, 3);
        mma_all(fa[0], fb[0]);          // ks 2
        CP_WAIT1();
        __syncthreads();
        if (i + 1 < NCH)
            ldfrag(fa[0], fb[0], sm0 + (uint32_t)((i + 1) % STAGES) * STAGE_BYTES, 0);
        mma_all(fa[1], fb[1]);          // ks 3
    }

    // ------------------------- epilogues -------------------------
    if constexpr (EPI == 5) {     // fused QKV: route by column section
        const int sect = bn >> 9;     // 0=Q, 1=K, 2=V
        #pragma unroll
        for (int mi = 0; mi < 4; mi++) {
            int row0 = bm + wm * 64 + mi * 16 + (lane >> 2);
            #pragma unroll
            for (int ni = 0; ni < 8; ni++) {
                int colg = bn + wn * 64 + ni * 8 + (lane & 3) * 2;
                int c    = colg & 511;
                if (sect == 0) {
                    __half2 h0 = __floats2half2_rn(acc[mi][ni][0] * scale, acc[mi][ni][1] * scale);
                    __half2 h1 = __floats2half2_rn(acc[mi][ni][2] * scale, acc[mi][ni][3] * scale);
                    *(__half2*)(g_Q + (size_t)row0       * DIM + c) = h0;
                    *(__half2*)(g_Q + (size_t)(row0 + 8) * DIM + c) = h1;
                } else if (sect == 1) {
                    __half2 h0 = __floats2half2_rn(acc[mi][ni][0], acc[mi][ni][1]);
                    __half2 h1 = __floats2half2_rn(acc[mi][ni][2], acc[mi][ni][3]);
                    *(__half2*)(g_K + (size_t)row0       * DIM + c) = h0;
                    *(__half2*)(g_K + (size_t)(row0 + 8) * DIM + c) = h1;
                } else {          // V transposed: Vt[b][dim][seq]
                    #pragma unroll
                    for (int e = 0; e < 4; e++) {
                        int m  = row0 + (e >> 1) * 8;
                        int cc = c + (e & 1);
                        int b  = m >> 12;
                        int sq = m & (NSEQ - 1);
                        g_Vt[(size_t)b * DIM * NSEQ + (size_t)cc * NSEQ + sq] =
                            __float2half(acc[mi][ni][e]);
                    }
                }
            }
        }
    } else if constexpr (EPI == 3) {   // exp2 epilogue (FMA pipe) + row partial sums
        __half* Cz = Ch + (size_t)z * sC;
        float rs[4][2] = {};
        #pragma unroll
        for (int mi = 0; mi < 4; mi++) {
            int row0 = bm + wm * 64 + mi * 16 + (lane >> 2);
            #pragma unroll
            for (int ni = 0; ni < 8; ni++) {
                int col = bn + wn * 64 + ni * 8 + (lane & 3) * 2;
                float e0 = exp2f_fast(acc[mi][ni][0] * scale);
                float e1 = exp2f_fast(acc[mi][ni][1] * scale);
                float e2 = exp2f_fast(acc[mi][ni][2] * scale);
                float e3 = exp2f_fast(acc[mi][ni][3] * scale);
                *(__half2*)(Cz + (size_t)row0       * ldC + col) = __floats2half2_rn(e0, e1);
                *(__half2*)(Cz + (size_t)(row0 + 8) * ldC + col) = __floats2half2_rn(e2, e3);
                rs[mi][0] += e0 + e1;
                rs[mi][1] += e2 + e3;
            }
        }
        __syncthreads();                    // stage smem no longer needed -> overlay
        float* psm = (float*)smem;          // [2][128]
        #pragma unroll
        for (int mi = 0; mi < 4; mi++)
            #pragma unroll
            for (int h = 0; h < 2; h++) {
                float t = rs[mi][h];
                t += __shfl_xor_sync(0xffffffffu, t, 1);
                t += __shfl_xor_sync(0xffffffffu, t, 2);
                if ((lane & 3) == 0)
                    psm[wn * 128 + wm * 64 + mi * 16 + (lane >> 2) + h * 8] = t;
            }
        __syncthreads();
        if (tid < 128) {
            float t = psm[tid] + psm[128 + tid];
            aux[(size_t)z * (NBT * NSEQ) + (size_t)blockIdx.x * NSEQ + bm + tid] = t;
        }
    } else {                      // EPI == 4: fp32 out, row-normalized
        float* base = Cf + (size_t)z * sC;
        const float* Rv = aux + (size_t)z * NSEQ;
        #pragma unroll
        for (int mi = 0; mi < 4; mi++) {
            int row0 = bm + wm * 64 + mi * 16 + (lane >> 2);
            float i0 = Rv[row0];
            float i1 = Rv[row0 + 8];
            #pragma unroll
            for (int ni = 0; ni < 8; ni++) {
                int col = bn + wn * 64 + ni * 8 + (lane & 3) * 2;
                *(float2*)(base + (size_t)row0       * ldC + col) =
                    make_float2(acc[mi][ni][0] * i0, acc[mi][ni][1] * i0);
                *(float2*)(base + (size_t)(row0 + 8) * ldC + col) =
                    make_float2(acc[mi][ni][2] * i1, acc[mi][ni][3] * i1);
            }
        }
    }
}

// ---------------------------------------------------------------------------
// fp32 -> fp16 convert, 4 elems/thread
// ---------------------------------------------------------------------------
__global__ __launch_bounds__(256)
void cvt_fp16(const float* __restrict__ in, __half* __restrict__ o, int n)
{
    int i = (blockIdx.x * 256 + threadIdx.x) * 4;
    if (i < n) {
        float4 v = *(const float4*)(in + i);
        *(__half2*)(o + i)     = __floats2half2_rn(v.x, v.y);
        *(__half2*)(o + i + 2) = __floats2half2_rn(v.z, v.w);
    }
}

// 3 weight tensors in one launch -> concatenated [1536,512]
__global__ __launch_bounds__(256)
void cvt_fp16_w(const float* __restrict__ w0, const float* __restrict__ w1,
                const float* __restrict__ w2, __half* __restrict__ o, int nw)
{
    int i = (blockIdx.x * 256 + threadIdx.x) * 4;
    const float* src = (i < nw) ? w0 : (i < 2 * nw) ? w1 : w2;
    int j = i - ((i < nw) ? 0 : (i < 2 * nw) ? nw : 2 * nw);
    float4 v = *(const float4*)(src + j);
    *(__half2*)(o + i)     = __floats2half2_rn(v.x, v.y);
    *(__half2*)(o + i + 2) = __floats2half2_rn(v.z, v.w);
}

// ---------------------------------------------------------------------------
// Reduce 32 partial sums per row -> reciprocal
// ---------------------------------------------------------------------------
__global__ __launch_bounds__(256)
void rowinv(const float* __restrict__ ps, float* __restrict__ ri)
{
    int r = blockIdx.x * 256 + threadIdx.x;   // 0..MTOT-1
    int z   = r >> 12;
    int row = r & (NSEQ - 1);
    const float* p = ps + (size_t)z * (NBT * NSEQ) + row;
    float s = 0.f;
    #pragma unroll
    for (int i = 0; i < NBT; i++) s += p[(size_t)i * NSEQ];
    ri[r] = 1.0f / s;
}

// ---------------------------------------------------------------------------
extern "C" void kernel_launch(void* const* d_in, const int* in_sizes, int n_in,
                              void* d_out, int out_size)
{
    const float* x  = (const float*)d_in[0];
    const float* wq = (const float*)d_in[1];
    const float* wk = (const float*)d_in[2];
    const float* wv = (const float*)d_in[3];
    float* out = (float*)d_out;

    __half *x16, *w16, *Q, *K, *Vt, *P;
    float *ps, *ri;
    cudaGetSymbolAddress((void**)&x16, g_x16);
    cudaGetSymbolAddress((void**)&w16, g_w16);
    cudaGetSymbolAddress((void**)&Q,  g_Q);
    cudaGetSymbolAddress((void**)&K,  g_K);
    cudaGetSymbolAddress((void**)&Vt, g_Vt);
    cudaGetSymbolAddress((void**)&P,  g_P);
    cudaGetSymbolAddress((void**)&ps, g_ps);
    cudaGetSymbolAddress((void**)&ri, g_ri);

    cudaFuncSetAttribute(mma_gemm<5>, cudaFuncAttributeMaxDynamicSharedMemorySize, SMEM_DYN);
    cudaFuncSetAttribute(mma_gemm<3>, cudaFuncAttributeMaxDynamicSharedMemorySize, SMEM_DYN);
    cudaFuncSetAttribute(mma_gemm<4>, cudaFuncAttributeMaxDynamicSharedMemorySize, SMEM_DYN);

    const int NX = MTOT * DIM;      // 8388608
    const int NW = DIM * DIM;       // 262144
    cvt_fp16<<<NX / 1024, 256>>>(x, x16, NX);
    cvt_fp16_w<<<3 * NW / 1024, 256>>>(wq, wk, wv, w16, NW);

    const float inv_sqrt_d = 0.04419417382415922f;            // 1/sqrt(512)
    const float scale_exp2 = inv_sqrt_d * 1.4426950408889634f; // fold log2(e)
    const dim3 blk(128);

    // Fused QKV projection: [16384,512] @ [1536,512]^T, epilogue routes
    // Q (scaled by 1/sqrt(d)), K, and V^T to their buffers.
    mma_gemm<5><<<dim3(12, 128, 1), blk, SMEM_DYN>>>(
        x16, w16, DIM, 0, 0, inv_sqrt_d, nullptr, nullptr, 0, 0, nullptr);

    // P~ = exp2(Q K^T * scale_exp2) per batch + row partial sums.
    // NOTE: Q is pre-scaled by 1/sqrt(d) already, so pass log2(e) only.
    mma_gemm<3><<<dim3(NBT, 32, BATCH), blk, SMEM_DYN>>>(
        Q, K, DIM, (size_t)NSEQ * DIM, (size_t)NSEQ * DIM, 1.4426950408889634f,
        nullptr, P, (size_t)NSEQ * NSEQ, NSEQ, ps);

    // 1 / row sums
    rowinv<<<MTOT / 256, 256>>>(ps, ri);

    // O = (P~ @ (V^T)^T) * rinv per batch (M=4096, N=512, K=4096)
    mma_gemm<4><<<dim3(4, 32, BATCH), blk, SMEM_DYN>>>(
        P, Vt, NSEQ, (size_t)NSEQ * NSEQ, (size_t)DIM * NSEQ, 1.0f,
        out, nullptr, (size_t)NSEQ * DIM, DIM, ri);
}

// round 15
// speedup vs baseline: 1.0465x; 1.0465x over previous
#include <cuda_runtime.h>
#include <cuda_fp16.h>
#include <cstdint>
#include <math.h>

#define BATCH   4
#define NSEQ    4096
#define DIM     512
#define MTOT    (BATCH*NSEQ)   // 16384
#define NBT     32             // N column tiles per batch in scores GEMM

// ---------------- scratch (allocation-free rule: device globals) ----------------
__device__ __align__(256) __half g_x16[(size_t)MTOT*DIM];
__device__ __align__(256) __half g_w16[3*DIM*DIM];   // [wq;wk;wv] = [1536,512]
__device__ __align__(256) __half g_Q [(size_t)MTOT*DIM];
__device__ __align__(256) __half g_K [(size_t)MTOT*DIM];
__device__ __align__(256) __half g_Vt[(size_t)BATCH*DIM*NSEQ];
__device__ __align__(256) __half g_P [(size_t)BATCH*NSEQ*NSEQ];   // unnormalized exp(S)
__device__ __align__(256) float  g_ps[(size_t)BATCH*NBT*NSEQ];    // per-CTA row partial sums
__device__ __align__(256) float  g_ri[(size_t)MTOT];              // 1 / row sum

// ---------------- helpers (plain sm_80-level PTX: valid on sm_103 target) -------
__device__ __forceinline__ uint32_t smem_to_u32(const void* p) {
    uint32_t a;
    asm("{ .reg .u64 t; cvta.to.shared.u64 t, %1; cvt.u32.u64 %0, t; }" : "=r"(a) : "l"(p));
    return a;
}
__device__ __forceinline__ void cp16(uint32_t dst, const void* src) {
    asm volatile("cp.async.cg.shared.global [%0], [%1], 16;" :: "r"(dst), "l"(src));
}
#define CP_COMMIT() asm volatile("cp.async.commit_group;")
#define CP_WAIT1()  asm volatile("cp.async.wait_group 1;")

#define LDSM_X4(r0,r1,r2,r3, addr) \
    asm volatile("ldmatrix.sync.aligned.m8n8.x4.shared.b16 {%0,%1,%2,%3}, [%4];" \
        : "=r"(r0), "=r"(r1), "=r"(r2), "=r"(r3) : "r"(addr))

#define MMA16816(d, a, b0, b1) \
    asm volatile("mma.sync.aligned.m16n8k16.row.col.f32.f16.f16.f32 " \
        "{%0,%1,%2,%3}, {%4,%5,%6,%7}, {%8,%9}, {%0,%1,%2,%3};" \
        : "+f"((d)[0]), "+f"((d)[1]), "+f"((d)[2]), "+f"((d)[3]) \
        : "r"((a)[0]), "r"((a)[1]), "r"((a)[2]), "r"((a)[3]), "r"(b0), "r"(b1))

// fp16-accumulate variant (d = 2x b32, each packing 2 halves)
#define MMA16816F16(d, a, b0, b1) \
    asm volatile("mma.sync.aligned.m16n8k16.row.col.f16.f16.f16.f16 " \
        "{%0,%1}, {%2,%3,%4,%5}, {%6,%7}, {%0,%1};" \
        : "+r"((d)[0]), "+r"((d)[1]) \
        : "r"((a)[0]), "r"((a)[1]), "r"((a)[2]), "r"((a)[3]), "r"(b0), "r"(b1))

// 16B-chunk XOR swizzle for [rows][64 half] tiles (128B rows, 8 chunks/row)
__device__ __forceinline__ uint32_t swz(int r, int c) {
    return (uint32_t)(r * 128 + ((c ^ (r & 7)) << 4));
}

// ---------------------------------------------------------------------------
// fp16 GEMM on mma.sync m16n8k16:  C[M,N] = scale * (A @ B^T)
// A: row-major M x K (fp16), B: row-major N x K (fp16).
// 128x128 CTA tile, BK=64, 3-stage cp.async pipeline in DYNAMIC smem (96KB),
// 4 warps (2m x 2n), 64x64 warp tile, 2-deep register fragment pipeline.
// ACC16=false: fp32 accumulators (projections, PV).
// ACC16=true : PURE fp16 accumulators (scores only: K=512, bounded partial
//              sums, no fp32 shadow -> no spills). Clean test of the
//              "fp32-acc HMMA is half-rate" hypothesis (round-11 retry,
//              minus the register-pressure confound).
// EPI: 3 = exp(acc*scale) -> fp16 P~ + per-CTA row partial sums to aux
//      4 = fp32 out * aux[row]  (row-wise normalization)
//      5 = fused QKV routing: col section 0 -> g_Q (*scale), 1 -> g_K,
//          2 -> g_Vt transposed.
// ---------------------------------------------------------------------------
#define STAGES      3
#define STAGE_BYTES 32768   // A 16KB + B 16KB
#define SMEM_DYN    (STAGES * STAGE_BYTES)

template<int EPI, bool ACC16>
__global__ __launch_bounds__(128, 2)
void mma_gemm(const __half* __restrict__ A, const __half* __restrict__ B,
              int K, size_t sA, size_t sB, float scale,
              float* __restrict__ Cf, __half* __restrict__ Ch,
              size_t sC, int ldC, float* __restrict__ aux)
{
    extern __shared__ __align__(1024) char smem[];
    const uint32_t sm0 = smem_to_u32(smem);
    const int tid  = threadIdx.x;
    const int wid  = tid >> 5;
    const int lane = tid & 31;
    const int wm   = wid & 1;        // 0..1  (64-row half)
    const int wn   = wid >> 1;       // 0..1  (64-col half)
    const int bm   = blockIdx.y * 128;
    const int bn   = blockIdx.x * 128;
    const int z    = blockIdx.z;

    const __half* Ap0 = A + (size_t)z * sA + (size_t)bm * K;
    const __half* Bp0 = B + (size_t)z * sB + (size_t)bn * K;

    const int NCH = K >> 6;     // 64-wide k chunks

    float    acc[ACC16 ? 1 : 4][8][4];
    uint32_t a16[ACC16 ? 4 : 1][8][2];
    if constexpr (!ACC16) {
        #pragma unroll
        for (int i = 0; i < 4; i++)
            #pragma unroll
            for (int j = 0; j < 8; j++)
                #pragma unroll
                for (int e = 0; e < 4; e++) acc[i][j][e] = 0.f;
    } else {
        #pragma unroll
        for (int i = 0; i < 4; i++)
            #pragma unroll
            for (int j = 0; j < 8; j++) { a16[i][j][0] = 0u; a16[i][j][1] = 0u; }
    }

    // stage load: A 128x64 + B 128x64; 16 cp.async per thread
    auto issue = [&](int i, int s) {
        const __half* Ap = Ap0 + (i << 6);
        const __half* Bp = Bp0 + (i << 6);
        uint32_t sa = sm0 + (uint32_t)s * STAGE_BYTES;
        #pragma unroll
        for (int u = 0; u < 8; u++) {
            int id = tid + u * 128;
            int r  = id >> 3;
            int c  = id & 7;
            uint32_t sw = swz(r, c);
            cp16(sa + sw,         Ap + (size_t)r * K + c * 8);
            cp16(sa + 16384 + sw, Bp + (size_t)r * K + c * 8);
        }
        CP_COMMIT();
    };

    auto ldfrag = [&](uint32_t (*fa)[4], uint32_t (*fb)[4], uint32_t sa, int ks) {
        #pragma unroll
        for (int mi = 0; mi < 4; mi++) {
            int r = wm * 64 + mi * 16 + (lane & 15);
            int c = 2 * ks + (lane >> 4);
            LDSM_X4(fa[mi][0], fa[mi][1], fa[mi][2], fa[mi][3], sa + swz(r, c));
        }
        #pragma unroll
        for (int g = 0; g < 4; g++) {
            int n = wn * 64 + g * 16 + (lane & 7) + ((lane >> 4) & 1) * 8;
            int c = 2 * ks + ((lane >> 3) & 1);
            LDSM_X4(fb[g][0], fb[g][1], fb[g][2], fb[g][3], sa + 16384 + swz(n, c));
        }
    };

    auto mma_all = [&](uint32_t (*fa)[4], uint32_t (*fb)[4]) {
        #pragma unroll
        for (int mi = 0; mi < 4; mi++)
            #pragma unroll
            for (int ni = 0; ni < 8; ni++) {
                if constexpr (ACC16)
                    MMA16816F16(a16[mi][ni], fa[mi],
                                fb[ni >> 1][(ni & 1) * 2], fb[ni >> 1][(ni & 1) * 2 + 1]);
                else
                    MMA16816(acc[mi][ni], fa[mi],
                             fb[ni >> 1][(ni & 1) * 2], fb[ni >> 1][(ni & 1) * 2 + 1]);
            }
    };

    uint32_t fa[2][4][4], fb[2][4][4];

    issue(0, 0);
    issue(1, 1);
    CP_WAIT1();
    __syncthreads();
    ldfrag(fa[0], fb[0], sm0, 0);

    for (int i = 0; i < NCH; i++) {
        uint32_t sa = sm0 + (uint32_t)(i % STAGES) * STAGE_BYTES;
        ldfrag(fa[1], fb[1], sa, 1);
        if (i + 2 < NCH) issue(i + 2, (i + 2) % STAGES); else CP_COMMIT();
        mma_all(fa[0], fb[0]);          // ks 0
        ldfrag(fa[0], fb[0], sa, 2);
        mma_all(fa[1], fb[1]);          // ks 1
        ldfrag(fa[1], fb[1], sa, 3);
        mma_all(fa[0], fb[0]);          // ks 2
        CP_WAIT1();
        __syncthreads();
        if (i + 1 < NCH)
            ldfrag(fa[0], fb[0], sm0 + (uint32_t)((i + 1) % STAGES) * STAGE_BYTES, 0);
        mma_all(fa[1], fb[1]);          // ks 3
    }

    // ------------------------- epilogues -------------------------
    if constexpr (EPI == 5) {     // fused QKV: route by column section
        const int sect = bn >> 9;     // 0=Q, 1=K, 2=V
        #pragma unroll
        for (int mi = 0; mi < 4; mi++) {
            int row0 = bm + wm * 64 + mi * 16 + (lane >> 2);
            #pragma unroll
            for (int ni = 0; ni < 8; ni++) {
                int colg = bn + wn * 64 + ni * 8 + (lane & 3) * 2;
                int c    = colg & 511;
                if (sect == 0) {
                    __half2 h0 = __floats2half2_rn(acc[mi][ni][0] * scale, acc[mi][ni][1] * scale);
                    __half2 h1 = __floats2half2_rn(acc[mi][ni][2] * scale, acc[mi][ni][3] * scale);
                    *(__half2*)(g_Q + (size_t)row0       * DIM + c) = h0;
                    *(__half2*)(g_Q + (size_t)(row0 + 8) * DIM + c) = h1;
                } else if (sect == 1) {
                    __half2 h0 = __floats2half2_rn(acc[mi][ni][0], acc[mi][ni][1]);
                    __half2 h1 = __floats2half2_rn(acc[mi][ni][2], acc[mi][ni][3]);
                    *(__half2*)(g_K + (size_t)row0       * DIM + c) = h0;
                    *(__half2*)(g_K + (size_t)(row0 + 8) * DIM + c) = h1;
                } else {          // V transposed: Vt[b][dim][seq]
                    #pragma unroll
                    for (int e = 0; e < 4; e++) {
                        int m  = row0 + (e >> 1) * 8;
                        int cc = c + (e & 1);
                        int b  = m >> 12;
                        int sq = m & (NSEQ - 1);
                        g_Vt[(size_t)b * DIM * NSEQ + (size_t)cc * NSEQ + sq] =
                            __float2half(acc[mi][ni][e]);
                    }
                }
            }
        }
    } else if constexpr (EPI == 3) {   // exp epilogue + row partial sums (fp16 acc)
        __half* Cz = Ch + (size_t)z * sC;
        float rs[4][2] = {};
        #pragma unroll
        for (int mi = 0; mi < 4; mi++) {
            int row0 = bm + wm * 64 + mi * 16 + (lane >> 2);
            #pragma unroll
            for (int ni = 0; ni < 8; ni++) {
                int col = bn + wn * 64 + ni * 8 + (lane & 3) * 2;
                float2 f0 = __half22float2(*(__half2*)&a16[mi][ni][0]);
                float2 f1 = __half22float2(*(__half2*)&a16[mi][ni][1]);
                float e0 = __expf(f0.x * scale);
                float e1 = __expf(f0.y * scale);
                float e2 = __expf(f1.x * scale);
                float e3 = __expf(f1.y * scale);
                *(__half2*)(Cz + (size_t)row0       * ldC + col) = __floats2half2_rn(e0, e1);
                *(__half2*)(Cz + (size_t)(row0 + 8) * ldC + col) = __floats2half2_rn(e2, e3);
                rs[mi][0] += e0 + e1;
                rs[mi][1] += e2 + e3;
            }
        }
        __syncthreads();                    // stage smem no longer needed -> overlay
        float* psm = (float*)smem;          // [2][128]
        #pragma unroll
        for (int mi = 0; mi < 4; mi++)
            #pragma unroll
            for (int h = 0; h < 2; h++) {
                float t = rs[mi][h];
                t += __shfl_xor_sync(0xffffffffu, t, 1);
                t += __shfl_xor_sync(0xffffffffu, t, 2);
                if ((lane & 3) == 0)
                    psm[wn * 128 + wm * 64 + mi * 16 + (lane >> 2) + h * 8] = t;
            }
        __syncthreads();
        if (tid < 128) {
            float t = psm[tid] + psm[128 + tid];
            aux[(size_t)z * (NBT * NSEQ) + (size_t)blockIdx.x * NSEQ + bm + tid] = t;
        }
    } else {                      // EPI == 4: fp32 out, row-normalized
        float* base = Cf + (size_t)z * sC;
        const float* Rv = aux + (size_t)z * NSEQ;
        #pragma unroll
        for (int mi = 0; mi < 4; mi++) {
            int row0 = bm + wm * 64 + mi * 16 + (lane >> 2);
            float i0 = Rv[row0];
            float i1 = Rv[row0 + 8];
            #pragma unroll
            for (int ni = 0; ni < 8; ni++) {
                int col = bn + wn * 64 + ni * 8 + (lane & 3) * 2;
                *(float2*)(base + (size_t)row0       * ldC + col) =
                    make_float2(acc[mi][ni][0] * i0, acc[mi][ni][1] * i0);
                *(float2*)(base + (size_t)(row0 + 8) * ldC + col) =
                    make_float2(acc[mi][ni][2] * i1, acc[mi][ni][3] * i1);
            }
        }
    }
}

// ---------------------------------------------------------------------------
// fp32 -> fp16 convert, 4 elems/thread
// ---------------------------------------------------------------------------
__global__ __launch_bounds__(256)
void cvt_fp16(const float* __restrict__ in, __half* __restrict__ o, int n)
{
    int i = (blockIdx.x * 256 + threadIdx.x) * 4;
    if (i < n) {
        float4 v = *(const float4*)(in + i);
        *(__half2*)(o + i)     = __floats2half2_rn(v.x, v.y);
        *(__half2*)(o + i + 2) = __floats2half2_rn(v.z, v.w);
    }
}

// 3 weight tensors in one launch -> concatenated [1536,512]
__global__ __launch_bounds__(256)
void cvt_fp16_w(const float* __restrict__ w0, const float* __restrict__ w1,
                const float* __restrict__ w2, __half* __restrict__ o, int nw)
{
    int i = (blockIdx.x * 256 + threadIdx.x) * 4;
    const float* src = (i < nw) ? w0 : (i < 2 * nw) ? w1 : w2;
    int j = i - ((i < nw) ? 0 : (i < 2 * nw) ? nw : 2 * nw);
    float4 v = *(const float4*)(src + j);
    *(__half2*)(o + i)     = __floats2half2_rn(v.x, v.y);
    *(__half2*)(o + i + 2) = __floats2half2_rn(v.z, v.w);
}

// ---------------------------------------------------------------------------
// Reduce 32 partial sums per row -> reciprocal
// ---------------------------------------------------------------------------
__global__ __launch_bounds__(256)
void rowinv(const float* __restrict__ ps, float* __restrict__ ri)
{
    int r = blockIdx.x * 256 + threadIdx.x;   // 0..MTOT-1
    int z   = r >> 12;
    int row = r & (NSEQ - 1);
    const float* p = ps + (size_t)z * (NBT * NSEQ) + row;
    float s = 0.f;
    #pragma unroll
    for (int i = 0; i < NBT; i++) s += p[(size_t)i * NSEQ];
    ri[r] = 1.0f / s;
}

// ---------------------------------------------------------------------------
extern "C" void kernel_launch(void* const* d_in, const int* in_sizes, int n_in,
                              void* d_out, int out_size)
{
    const float* x  = (const float*)d_in[0];
    const float* wq = (const float*)d_in[1];
    const float* wk = (const float*)d_in[2];
    const float* wv = (const float*)d_in[3];
    float* out = (float*)d_out;

    __half *x16, *w16, *Q, *K, *Vt, *P;
    float *ps, *ri;
    cudaGetSymbolAddress((void**)&x16, g_x16);
    cudaGetSymbolAddress((void**)&w16, g_w16);
    cudaGetSymbolAddress((void**)&Q,  g_Q);
    cudaGetSymbolAddress((void**)&K,  g_K);
    cudaGetSymbolAddress((void**)&Vt, g_Vt);
    cudaGetSymbolAddress((void**)&P,  g_P);
    cudaGetSymbolAddress((void**)&ps, g_ps);
    cudaGetSymbolAddress((void**)&ri, g_ri);

    cudaFuncSetAttribute((const void*)mma_gemm<5, false>, cudaFuncAttributeMaxDynamicSharedMemorySize, SMEM_DYN);
    cudaFuncSetAttribute((const void*)mma_gemm<3, true>,  cudaFuncAttributeMaxDynamicSharedMemorySize, SMEM_DYN);
    cudaFuncSetAttribute((const void*)mma_gemm<4, false>, cudaFuncAttributeMaxDynamicSharedMemorySize, SMEM_DYN);

    const int NX = MTOT * DIM;      // 8388608
    const int NW = DIM * DIM;       // 262144
    cvt_fp16<<<NX / 1024, 256>>>(x, x16, NX);
    cvt_fp16_w<<<3 * NW / 1024, 256>>>(wq, wk, wv, w16, NW);

    const float inv_sqrt_d = 0.04419417382415922f;  // 1/sqrt(512)
    const dim3 blk(128);

    // Fused QKV projection (fp32-acc): [16384,512] @ [1536,512]^T; epilogue
    // routes Q (scaled by 1/sqrt(d)), K, and V^T.
    mma_gemm<5, false><<<dim3(12, 128, 1), blk, SMEM_DYN>>>(
        x16, w16, DIM, 0, 0, inv_sqrt_d, nullptr, nullptr, 0, 0, nullptr);

    // P~ = exp(Q K^T) per batch + row partial sums. fp16-acc (clean rate test:
    // K=512, bounded sums, no fp32 shadow, no spills). Q carries 1/sqrt(d).
    mma_gemm<3, true><<<dim3(NBT, 32, BATCH), blk, SMEM_DYN>>>(
        Q, K, DIM, (size_t)NSEQ * DIM, (size_t)NSEQ * DIM, 1.0f,
        nullptr, P, (size_t)NSEQ * NSEQ, NSEQ, ps);

    // 1 / row sums
    rowinv<<<MTOT / 256, 256>>>(ps, ri);

    // O = (P~ @ (V^T)^T) * rinv per batch (M=4096, N=512, K=4096), fp32-acc
    mma_gemm<4, false><<<dim3(4, 32, BATCH), blk, SMEM_DYN>>>(
        P, Vt, NSEQ, (size_t)NSEQ * NSEQ, (size_t)DIM * NSEQ, 1.0f,
        out, nullptr, (size_t)NSEQ * DIM, DIM, ri);
}

// round 16
// speedup vs baseline: 1.0607x; 1.0136x over previous
#include <cuda_runtime.h>
#include <cuda_fp16.h>
#include <cstdint>
#include <math.h>

#define BATCH   4
#define NSEQ    4096
#define DIM     512
#define MTOT    (BATCH*NSEQ)   // 16384
#define NBT     32             // N column tiles per batch in scores GEMM

// ---------------- scratch (allocation-free rule: device globals) ----------------
__device__ __align__(256) __half g_x16[(size_t)MTOT*DIM];
__device__ __align__(256) __half g_w16[3*DIM*DIM];   // [wq;wk;wv] = [1536,512]
__device__ __align__(256) __half g_Q [(size_t)MTOT*DIM];
__device__ __align__(256) __half g_K [(size_t)MTOT*DIM];
__device__ __align__(256) __half g_Vt[(size_t)BATCH*DIM*NSEQ];
__device__ __align__(256) __half g_P [(size_t)BATCH*NSEQ*NSEQ];   // unnormalized exp(S)
__device__ __align__(256) float  g_ps[(size_t)BATCH*NBT*NSEQ];    // per-CTA row partial sums

// ---------------- helpers (plain sm_80-level PTX: valid on sm_103 target) -------
__device__ __forceinline__ uint32_t smem_to_u32(const void* p) {
    uint32_t a;
    asm("{ .reg .u64 t; cvta.to.shared.u64 t, %1; cvt.u32.u64 %0, t; }" : "=r"(a) : "l"(p));
    return a;
}
__device__ __forceinline__ void cp16(uint32_t dst, const void* src) {
    asm volatile("cp.async.cg.shared.global [%0], [%1], 16;" :: "r"(dst), "l"(src));
}
#define CP_COMMIT() asm volatile("cp.async.commit_group;")
#define CP_WAIT1()  asm volatile("cp.async.wait_group 1;")

#define LDSM_X4(r0,r1,r2,r3, addr) \
    asm volatile("ldmatrix.sync.aligned.m8n8.x4.shared.b16 {%0,%1,%2,%3}, [%4];" \
        : "=r"(r0), "=r"(r1), "=r"(r2), "=r"(r3) : "r"(addr))

#define MMA16816(d, a, b0, b1) \
    asm volatile("mma.sync.aligned.m16n8k16.row.col.f32.f16.f16.f32 " \
        "{%0,%1,%2,%3}, {%4,%5,%6,%7}, {%8,%9}, {%0,%1,%2,%3};" \
        : "+f"((d)[0]), "+f"((d)[1]), "+f"((d)[2]), "+f"((d)[3]) \
        : "r"((a)[0]), "r"((a)[1]), "r"((a)[2]), "r"((a)[3]), "r"(b0), "r"(b1))

// fp16-accumulate variant (d = 2x b32, each packing 2 halves)
#define MMA16816F16(d, a, b0, b1) \
    asm volatile("mma.sync.aligned.m16n8k16.row.col.f16.f16.f16.f16 " \
        "{%0,%1}, {%2,%3,%4,%5}, {%6,%7}, {%0,%1};" \
        : "+r"((d)[0]), "+r"((d)[1]) \
        : "r"((a)[0]), "r"((a)[1]), "r"((a)[2]), "r"((a)[3]), "r"(b0), "r"(b1))

// 16B-chunk XOR swizzle for [rows][64 half] tiles (128B rows, 8 chunks/row)
__device__ __forceinline__ uint32_t swz(int r, int c) {
    return (uint32_t)(r * 128 + ((c ^ (r & 7)) << 4));
}

// ---------------------------------------------------------------------------
// fp16 GEMM on mma.sync m16n8k16:  C[M,N] = scale * (A @ B^T)
// A: row-major M x K (fp16), B: row-major N x K (fp16).
// 128x128 CTA tile, BK=64, 3-stage cp.async pipeline in DYNAMIC smem (96KB
// + 512B ri extension for EPI4), 4 warps (2m x 2n), 64x64 warp tile,
// 2-deep register fragment pipeline.
// ACC16=false: fp32 accumulators (QKV, PV).
// ACC16=true : pure fp16 accumulators (scores; K=512 bounded sums — round-15
//              measurement: same HMMA rate, fewer regs).
// EPI: 3 = exp(acc*scale) -> fp16 P~ + per-CTA row partial sums to aux
//      4 = fp32 out, row-normalized; ri computed IN-KERNEL from aux (=ps)
//          during the pipeline-fill shadow (rowinv kernel fused away)
//      5 = fused QKV routing: col section 0 -> g_Q (*scale), 1 -> g_K,
//          2 -> g_Vt transposed.
// ---------------------------------------------------------------------------
#define STAGES      3
#define STAGE_BYTES 32768   // A 16KB + B 16KB
#define SMEM_DYN    (STAGES * STAGE_BYTES)
#define SMEM_DYN_RI (SMEM_DYN + 512)

template<int EPI, bool ACC16>
__global__ __launch_bounds__(128, 2)
void mma_gemm(const __half* __restrict__ A, const __half* __restrict__ B,
              int K, size_t sA, size_t sB, float scale,
              float* __restrict__ Cf, __half* __restrict__ Ch,
              size_t sC, int ldC, float* __restrict__ aux)
{
    extern __shared__ __align__(1024) char smem[];
    const uint32_t sm0 = smem_to_u32(smem);
    const int tid  = threadIdx.x;
    const int wid  = tid >> 5;
    const int lane = tid & 31;
    const int wm   = wid & 1;        // 0..1  (64-row half)
    const int wn   = wid >> 1;       // 0..1  (64-col half)
    const int bm   = blockIdx.y * 128;
    const int bn   = blockIdx.x * 128;
    const int z    = blockIdx.z;

    const __half* Ap0 = A + (size_t)z * sA + (size_t)bm * K;
    const __half* Bp0 = B + (size_t)z * sB + (size_t)bn * K;

    const int NCH = K >> 6;     // 64-wide k chunks

    float    acc[ACC16 ? 1 : 4][8][4];
    uint32_t a16[ACC16 ? 4 : 1][8][2];
    if constexpr (!ACC16) {
        #pragma unroll
        for (int i = 0; i < 4; i++)
            #pragma unroll
            for (int j = 0; j < 8; j++)
                #pragma unroll
                for (int e = 0; e < 4; e++) acc[i][j][e] = 0.f;
    } else {
        #pragma unroll
        for (int i = 0; i < 4; i++)
            #pragma unroll
            for (int j = 0; j < 8; j++) { a16[i][j][0] = 0u; a16[i][j][1] = 0u; }
    }

    // stage load: A 128x64 + B 128x64; 16 cp.async per thread
    auto issue = [&](int i, int s) {
        const __half* Ap = Ap0 + (i << 6);
        const __half* Bp = Bp0 + (i << 6);
        uint32_t sa = sm0 + (uint32_t)s * STAGE_BYTES;
        #pragma unroll
        for (int u = 0; u < 8; u++) {
            int id = tid + u * 128;
            int r  = id >> 3;
            int c  = id & 7;
            uint32_t sw = swz(r, c);
            cp16(sa + sw,         Ap + (size_t)r * K + c * 8);
            cp16(sa + 16384 + sw, Bp + (size_t)r * K + c * 8);
        }
        CP_COMMIT();
    };

    auto ldfrag = [&](uint32_t (*fa)[4], uint32_t (*fb)[4], uint32_t sa, int ks) {
        #pragma unroll
        for (int mi = 0; mi < 4; mi++) {
            int r = wm * 64 + mi * 16 + (lane & 15);
            int c = 2 * ks + (lane >> 4);
            LDSM_X4(fa[mi][0], fa[mi][1], fa[mi][2], fa[mi][3], sa + swz(r, c));
        }
        #pragma unroll
        for (int g = 0; g < 4; g++) {
            int n = wn * 64 + g * 16 + (lane & 7) + ((lane >> 4) & 1) * 8;
            int c = 2 * ks + ((lane >> 3) & 1);
            LDSM_X4(fb[g][0], fb[g][1], fb[g][2], fb[g][3], sa + 16384 + swz(n, c));
        }
    };

    auto mma_all = [&](uint32_t (*fa)[4], uint32_t (*fb)[4]) {
        #pragma unroll
        for (int mi = 0; mi < 4; mi++)
            #pragma unroll
            for (int ni = 0; ni < 8; ni++) {
                if constexpr (ACC16)
                    MMA16816F16(a16[mi][ni], fa[mi],
                                fb[ni >> 1][(ni & 1) * 2], fb[ni >> 1][(ni & 1) * 2 + 1]);
                else
                    MMA16816(acc[mi][ni], fa[mi],
                             fb[ni >> 1][(ni & 1) * 2], fb[ni >> 1][(ni & 1) * 2 + 1]);
            }
    };

    uint32_t fa[2][4][4], fb[2][4][4];

    issue(0, 0);
    issue(1, 1);

    // EPI4: compute this tile's 128 reciprocal row-sums from ps while the
    // first two cp.async stages are in flight (fused former rowinv kernel).
    // Same per-row summation order as the old kernel -> bit-identical output.
    if constexpr (EPI == 4) {
        float* ris = (float*)(smem + SMEM_DYN);
        const float* p = aux + (size_t)z * (NBT * NSEQ) + bm + tid;
        float s = 0.f;
        #pragma unroll
        for (int i = 0; i < NBT; i++) s += p[(size_t)i * NSEQ];
        ris[tid] = 1.0f / s;
        // visibility to other threads is covered by the mainloop __syncthreads
    }

    CP_WAIT1();
    __syncthreads();
    ldfrag(fa[0], fb[0], sm0, 0);

    for (int i = 0; i < NCH; i++) {
        uint32_t sa = sm0 + (uint32_t)(i % STAGES) * STAGE_BYTES;
        ldfrag(fa[1], fb[1], sa, 1);
        if (i + 2 < NCH) issue(i + 2, (i + 2) % STAGES); else CP_COMMIT();
        mma_all(fa[0], fb[0]);          // ks 0
        ldfrag(fa[0], fb[0], sa, 2);
        mma_all(fa[1], fb[1]);          // ks 1
        ldfrag(fa[1], fb[1], sa, 3);
        mma_all(fa[0], fb[0]);          // ks 2
        CP_WAIT1();
        __syncthreads();
        if (i + 1 < NCH)
            ldfrag(fa[0], fb[0], sm0 + (uint32_t)((i + 1) % STAGES) * STAGE_BYTES, 0);
        mma_all(fa[1], fb[1]);          // ks 3
    }

    // ------------------------- epilogues -------------------------
    if constexpr (EPI == 5) {     // fused QKV: route by column section
        const int sect = bn >> 9;     // 0=Q, 1=K, 2=V
        #pragma unroll
        for (int mi = 0; mi < 4; mi++) {
            int row0 = bm + wm * 64 + mi * 16 + (lane >> 2);
            #pragma unroll
            for (int ni = 0; ni < 8; ni++) {
                int colg = bn + wn * 64 + ni * 8 + (lane & 3) * 2;
                int c    = colg & 511;
                if (sect == 0) {
                    __half2 h0 = __floats2half2_rn(acc[mi][ni][0] * scale, acc[mi][ni][1] * scale);
                    __half2 h1 = __floats2half2_rn(acc[mi][ni][2] * scale, acc[mi][ni][3] * scale);
                    *(__half2*)(g_Q + (size_t)row0       * DIM + c) = h0;
                    *(__half2*)(g_Q + (size_t)(row0 + 8) * DIM + c) = h1;
                } else if (sect == 1) {
                    __half2 h0 = __floats2half2_rn(acc[mi][ni][0], acc[mi][ni][1]);
                    __half2 h1 = __floats2half2_rn(acc[mi][ni][2], acc[mi][ni][3]);
                    *(__half2*)(g_K + (size_t)row0       * DIM + c) = h0;
                    *(__half2*)(g_K + (size_t)(row0 + 8) * DIM + c) = h1;
                } else {          // V transposed: Vt[b][dim][seq]
                    #pragma unroll
                    for (int e = 0; e < 4; e++) {
                        int m  = row0 + (e >> 1) * 8;
                        int cc = c + (e & 1);
                        int b  = m >> 12;
                        int sq = m & (NSEQ - 1);
                        g_Vt[(size_t)b * DIM * NSEQ + (size_t)cc * NSEQ + sq] =
                            __float2half(acc[mi][ni][e]);
                    }
                }
            }
        }
    } else if constexpr (EPI == 3) {   // exp epilogue + row partial sums (fp16 acc)
        __half* Cz = Ch + (size_t)z * sC;
        float rs[4][2] = {};
        #pragma unroll
        for (int mi = 0; mi < 4; mi++) {
            int row0 = bm + wm * 64 + mi * 16 + (lane >> 2);
            #pragma unroll
            for (int ni = 0; ni < 8; ni++) {
                int col = bn + wn * 64 + ni * 8 + (lane & 3) * 2;
                float2 f0 = __half22float2(*(__half2*)&a16[mi][ni][0]);
                float2 f1 = __half22float2(*(__half2*)&a16[mi][ni][1]);
                float e0 = __expf(f0.x * scale);
                float e1 = __expf(f0.y * scale);
                float e2 = __expf(f1.x * scale);
                float e3 = __expf(f1.y * scale);
                *(__half2*)(Cz + (size_t)row0       * ldC + col) = __floats2half2_rn(e0, e1);
                *(__half2*)(Cz + (size_t)(row0 + 8) * ldC + col) = __floats2half2_rn(e2, e3);
                rs[mi][0] += e0 + e1;
                rs[mi][1] += e2 + e3;
            }
        }
        __syncthreads();                    // stage smem no longer needed -> overlay
        float* psm = (float*)smem;          // [2][128]
        #pragma unroll
        for (int mi = 0; mi < 4; mi++)
            #pragma unroll
            for (int h = 0; h < 2; h++) {
                float t = rs[mi][h];
                t += __shfl_xor_sync(0xffffffffu, t, 1);
                t += __shfl_xor_sync(0xffffffffu, t, 2);
                if ((lane & 3) == 0)
                    psm[wn * 128 + wm * 64 + mi * 16 + (lane >> 2) + h * 8] = t;
            }
        __syncthreads();
        if (tid < 128) {
            float t = psm[tid] + psm[128 + tid];
            aux[(size_t)z * (NBT * NSEQ) + (size_t)blockIdx.x * NSEQ + bm + tid] = t;
        }
    } else {                      // EPI == 4: fp32 out, row-normalized (ri in smem)
        float* base = Cf + (size_t)z * sC;
        const float* ris = (const float*)(smem + SMEM_DYN);
        #pragma unroll
        for (int mi = 0; mi < 4; mi++) {
            int r0 = wm * 64 + mi * 16 + (lane >> 2);
            int row0 = bm + r0;
            float i0 = ris[r0];
            float i1 = ris[r0 + 8];
            #pragma unroll
            for (int ni = 0; ni < 8; ni++) {
                int col = bn + wn * 64 + ni * 8 + (lane & 3) * 2;
                *(float2*)(base + (size_t)row0       * ldC + col) =
                    make_float2(acc[mi][ni][0] * i0, acc[mi][ni][1] * i0);
                *(float2*)(base + (size_t)(row0 + 8) * ldC + col) =
                    make_float2(acc[mi][ni][2] * i1, acc[mi][ni][3] * i1);
            }
        }
    }
}

// ---------------------------------------------------------------------------
// Single fused fp32 -> fp16 convert for x + 3 weight tensors (one launch).
// 4 elems/thread; regions: [0,nx) -> x, then nw-sized chunks for w0/w1/w2.
// ---------------------------------------------------------------------------
__global__ __launch_bounds__(256)
void cvt_all(const float* __restrict__ x,
             const float* __restrict__ w0, const float* __restrict__ w1,
             const float* __restrict__ w2,
             __half* __restrict__ ox, __half* __restrict__ ow,
             int nx, int nw)
{
    int i = (blockIdx.x * 256 + threadIdx.x) * 4;
    const float* src;
    __half* dst;
    int j;
    if (i < nx)                { src = x;  dst = ox; j = i; }
    else {
        int k = i - nx;
        dst = ow;
        if (k < nw)            { src = w0; j = k; }
        else if (k < 2 * nw)   { src = w1; j = k - nw; }
        else                   { src = w2; j = k - 2 * nw; }
        dst = ow + (k - j ? (k - j) : 0) - (k - j) + k;  // dst index = k
        // (simplified below)
    }
    if (i < nx) {
        float4 v = *(const float4*)(x + i);
        *(__half2*)(ox + i)     = __floats2half2_rn(v.x, v.y);
        *(__half2*)(ox + i + 2) = __floats2half2_rn(v.z, v.w);
    } else {
        int k = i - nx;
        const float* s = (k < nw) ? w0 : (k < 2 * nw) ? w1 : w2;
        int jj = k - ((k < nw) ? 0 : (k < 2 * nw) ? nw : 2 * nw);
        float4 v = *(const float4*)(s + jj);
        *(__half2*)(ow + k)     = __floats2half2_rn(v.x, v.y);
        *(__half2*)(ow + k + 2) = __floats2half2_rn(v.z, v.w);
    }
}

// ---------------------------------------------------------------------------
extern "C" void kernel_launch(void* const* d_in, const int* in_sizes, int n_in,
                              void* d_out, int out_size)
{
    const float* x  = (const float*)d_in[0];
    const float* wq = (const float*)d_in[1];
    const float* wk = (const float*)d_in[2];
    const float* wv = (const float*)d_in[3];
    float* out = (float*)d_out;

    __half *x16, *w16, *Q, *K, *Vt, *P;
    float *ps;
    cudaGetSymbolAddress((void**)&x16, g_x16);
    cudaGetSymbolAddress((void**)&w16, g_w16);
    cudaGetSymbolAddress((void**)&Q,  g_Q);
    cudaGetSymbolAddress((void**)&K,  g_K);
    cudaGetSymbolAddress((void**)&Vt, g_Vt);
    cudaGetSymbolAddress((void**)&P,  g_P);
    cudaGetSymbolAddress((void**)&ps, g_ps);

    cudaFuncSetAttribute((const void*)mma_gemm<5, false>, cudaFuncAttributeMaxDynamicSharedMemorySize, SMEM_DYN);
    cudaFuncSetAttribute((const void*)mma_gemm<3, true>,  cudaFuncAttributeMaxDynamicSharedMemorySize, SMEM_DYN);
    cudaFuncSetAttribute((const void*)mma_gemm<4, false>, cudaFuncAttributeMaxDynamicSharedMemorySize, SMEM_DYN_RI);

    const int NX = MTOT * DIM;      // 8388608
    const int NW = DIM * DIM;       // 262144

    // One convert launch for x + all three weights
    cvt_all<<<(NX + 3 * NW) / 1024, 256>>>(x, wq, wk, wv, x16, w16, NX, NW);

    const float inv_sqrt_d = 0.04419417382415922f;  // 1/sqrt(512)
    const dim3 blk(128);

    // Fused QKV projection (fp32-acc): [16384,512] @ [1536,512]^T; epilogue
    // routes Q (scaled by 1/sqrt(d)), K, and V^T.
    mma_gemm<5, false><<<dim3(12, 128, 1), blk, SMEM_DYN>>>(
        x16, w16, DIM, 0, 0, inv_sqrt_d, nullptr, nullptr, 0, 0, nullptr);

    // P~ = exp(Q K^T) per batch + row partial sums (fp16 acc; Q carries 1/sqrt(d)).
    mma_gemm<3, true><<<dim3(NBT, 32, BATCH), blk, SMEM_DYN>>>(
        Q, K, DIM, (size_t)NSEQ * DIM, (size_t)NSEQ * DIM, 1.0f,
        nullptr, P, (size_t)NSEQ * NSEQ, NSEQ, ps);

    // O = (P~ @ (V^T)^T) * rinv per batch (M=4096, N=512, K=4096), fp32-acc.
    // rinv computed in-kernel from ps during pipeline fill (rowinv fused).
    mma_gemm<4, false><<<dim3(4, 32, BATCH), blk, SMEM_DYN_RI>>>(
        P, Vt, NSEQ, (size_t)NSEQ * NSEQ, (size_t)DIM * NSEQ, 1.0f,
        out, nullptr, (size_t)NSEQ * DIM, DIM, ps);
}